// round 4
// baseline (speedup 1.0000x reference)
#include <cuda_runtime.h>
#include <math.h>

#define B   8
#define C   64
#define T   4096
#define KNN 9

typedef unsigned long long u64;

// Scratch (allocation-free: __device__ globals)
__device__ float g_qT[B * T * C];          // normalized q, [b][t][c]
__device__ float g_kT[B * T * C];          // normalized k, [b][t][c]
__device__ float g_vT[B * T * C];          // v, [b][t][c]
__device__ float g_wP[KNN * C * C];        // conv_w permuted: [kk][cc][o]
__device__ int   g_idx[B * T * KNN];       // top-9 neighbor indices per (b,i)

// ---------------------------------------------------------------------------
// Packed fp32x2 helpers (sm_100+): each lane is an exact IEEE rn fp32 op.
// ---------------------------------------------------------------------------
__device__ __forceinline__ u64 pk2(float lo, float hi) {
    u64 r; asm("mov.b64 %0, {%1, %2};" : "=l"(r) : "f"(lo), "f"(hi)); return r;
}
__device__ __forceinline__ u64 fma2(u64 a, u64 b, u64 c) {
    u64 d; asm("fma.rn.f32x2 %0, %1, %2, %3;" : "=l"(d) : "l"(a), "l"(b), "l"(c));
    return d;
}
__device__ __forceinline__ void unpk(u64 v, float& lo, float& hi) {
    asm("mov.b64 {%0, %1}, %2;" : "=f"(lo), "=f"(hi) : "l"(v));
}

// ---------------------------------------------------------------------------
// Kernel 0: permute conv_w[o][cc*9+kk] -> wP[kk][cc][o]
// ---------------------------------------------------------------------------
__global__ void permute_w_kernel(const float* __restrict__ conv_w) {
    int s = blockIdx.x * 256 + threadIdx.x;
    if (s < KNN * C * C) {
        int o  = s & 63;
        int cc = (s >> 6) & 63;
        int kk = s >> 12;
        g_wP[s] = conv_w[o * (C * KNN) + cc * KNN + kk];
    }
}

// ---------------------------------------------------------------------------
// Kernel 1: q/k/v projections + L2 normalize (k,q), write transposed [b][t][c]
// Numerics: sequential fused FMA over c; separate mul+add for sum-of-squares;
// IEEE division by fmax(sqrt, 1e-12). (Matched reference at 5e-7 in R3.)
// ---------------------------------------------------------------------------
__global__ __launch_bounds__(128) void proj_kernel(
    const float* __restrict__ x,
    const float* __restrict__ Wq,
    const float* __restrict__ Wk,
    const float* __restrict__ Wv)
{
    __shared__ float Xs[C][128];   // 32 KB
    __shared__ float Ws[C][C];     // 16 KB, [c][d]

    const int b   = blockIdx.y;
    const int t0  = blockIdx.x * 128;
    const int tid = threadIdx.x;

    const float* xb = x + (size_t)b * C * T;
    for (int c = 0; c < C; c++)
        Xs[c][tid] = xb[c * T + t0 + tid];

    for (int m = 0; m < 3; m++) {
        const float* W = (m == 0) ? Wq : ((m == 1) ? Wk : Wv);
        float* dstbase = (m == 0) ? g_qT : ((m == 1) ? g_kT : g_vT);

        __syncthreads();
        for (int s = tid; s < C * C; s += 128) {
            int c = s >> 6, d = s & 63;
            Ws[c][d] = W[d * C + c];
        }
        __syncthreads();

        float acc[C];
        #pragma unroll
        for (int d = 0; d < C; d++) acc[d] = 0.f;

        for (int c = 0; c < C; c++) {
            float xv = Xs[c][tid];
            const float4* wr = (const float4*)Ws[c];
            #pragma unroll
            for (int d4 = 0; d4 < 16; d4++) {
                float4 w = wr[d4];
                acc[4*d4+0] = __fmaf_rn(w.x, xv, acc[4*d4+0]);
                acc[4*d4+1] = __fmaf_rn(w.y, xv, acc[4*d4+1]);
                acc[4*d4+2] = __fmaf_rn(w.z, xv, acc[4*d4+2]);
                acc[4*d4+3] = __fmaf_rn(w.w, xv, acc[4*d4+3]);
            }
        }

        if (m < 2) {
            float ss = 0.f;
            #pragma unroll
            for (int d = 0; d < C; d++)
                ss = __fadd_rn(ss, __fmul_rn(acc[d], acc[d]));
            float n = fmaxf(sqrtf(ss), 1e-12f);
            #pragma unroll
            for (int d = 0; d < C; d++)
                acc[d] = __fdiv_rn(acc[d], n);
        }

        float4* dst = (float4*)(dstbase + ((size_t)b * T + t0 + tid) * C);
        #pragma unroll
        for (int d4 = 0; d4 < 16; d4++)
            dst[d4] = make_float4(acc[4*d4+0], acc[4*d4+1], acc[4*d4+2], acc[4*d4+3]);
    }
}

// ---------------------------------------------------------------------------
// Top-9 sorted-descending state (strict > preserves jax top_k tie-breaking
// when candidates are inserted in ascending index order).
// ---------------------------------------------------------------------------
struct Top9 {
    float v0,v1,v2,v3,v4,v5,v6,v7,v8;
    int   j0,j1,j2,j3,j4,j5,j6,j7,j8;
    __device__ __forceinline__ void init() {
        v0=v1=v2=v3=v4=v5=v6=v7=v8 = -1.f;
        j0=j1=j2=j3=j4=j5=j6=j7=j8 = 0;
    }
    __device__ __forceinline__ void insert(float s, int j) {
        if (s > v8) {
            v8 = s; j8 = j;
            #define _CSW(va,ja,vb,jb) if ((vb) > (va)) { float tv=(va); (va)=(vb); (vb)=tv; int tj=(ja); (ja)=(jb); (jb)=tj; }
            _CSW(v7,j7,v8,j8); _CSW(v6,j6,v7,j7); _CSW(v5,j5,v6,j6);
            _CSW(v4,j4,v5,j5); _CSW(v3,j3,v4,j4); _CSW(v2,j2,v3,j3);
            _CSW(v1,j1,v2,j2); _CSW(v0,j0,v1,j1);
            #undef _CSW
        }
    }
    __device__ __forceinline__ void store(int* op) {
        op[0]=j0; op[1]=j1; op[2]=j2; op[3]=j3; op[4]=j4;
        op[5]=j5; op[6]=j6; op[7]=j7; op[8]=j8;
    }
};

// ---------------------------------------------------------------------------
// Kernel 2: fused sim + top-9, f32x2 packed across TWO i-rows per thread.
//  - k pair (k_i0[c], k_i1[c]) packed into 64 resident 64-bit regs
//  - q tile duplicated in smem: QsD[j][c] = (q_j[c], q_j[c]) -> zero pack ALU
//  - per candidate, strictly sequential fp32 FMA chain over c = 0..63
//  Inner loop per 2 channels x 4 candidates: 4x LDS.128 (broadcast) + 8 FFMA2.
// ---------------------------------------------------------------------------
__global__ __launch_bounds__(128) void sim_topk_kernel()
{
    __shared__ __align__(16) u64 QsD[64 * C];   // 32 KB: [j][c] dup-pairs

    const int b   = blockIdx.y;
    const int tid = threadIdx.x;
    const int i0  = blockIdx.x * 256 + tid;
    const int i1  = i0 + 128;

    // pack k rows for i0 (lo lane) and i1 (hi lane)
    u64 kp[C];
    {
        const float4* k0 = (const float4*)(g_kT + ((size_t)b * T + i0) * C);
        const float4* k1 = (const float4*)(g_kT + ((size_t)b * T + i1) * C);
        #pragma unroll
        for (int c4 = 0; c4 < 16; c4++) {
            float4 a = k0[c4], bb = k1[c4];
            kp[4*c4+0] = pk2(a.x, bb.x);
            kp[4*c4+1] = pk2(a.y, bb.y);
            kp[4*c4+2] = pk2(a.z, bb.z);
            kp[4*c4+3] = pk2(a.w, bb.w);
        }
    }

    Top9 tA, tB;
    tA.init(); tB.init();

    for (int jt = 0; jt < T; jt += 64) {
        __syncthreads();
        // stage 64 q rows, duplicated to 8B pairs
        #pragma unroll
        for (int u = 0; u < 8; u++) {
            int idx = u * 128 + tid;           // 0..1023 = 64 j x 16 c4
            int j   = idx >> 4;
            int c4  = idx & 15;
            float4 q = ((const float4*)(g_qT + ((size_t)b * T + jt + j) * C))[c4];
            u64* dst = &QsD[j * C + c4 * 4];
            dst[0] = pk2(q.x, q.x);
            dst[1] = pk2(q.y, q.y);
            dst[2] = pk2(q.z, q.z);
            dst[3] = pk2(q.w, q.w);
        }
        __syncthreads();

        for (int jj = 0; jj < 64; jj += 4) {
            const ulonglong2* q0 = (const ulonglong2*)&QsD[(jj + 0) * C];
            const ulonglong2* q1 = (const ulonglong2*)&QsD[(jj + 1) * C];
            const ulonglong2* q2 = (const ulonglong2*)&QsD[(jj + 2) * C];
            const ulonglong2* q3 = (const ulonglong2*)&QsD[(jj + 3) * C];
            u64 s0 = 0ull, s1 = 0ull, s2 = 0ull, s3 = 0ull;
            #pragma unroll
            for (int c2 = 0; c2 < 32; c2++) {
                ulonglong2 a = q0[c2], bq = q1[c2], cq = q2[c2], dq = q3[c2];
                s0 = fma2(kp[2*c2],   a.x,  s0);
                s1 = fma2(kp[2*c2],   bq.x, s1);
                s2 = fma2(kp[2*c2],   cq.x, s2);
                s3 = fma2(kp[2*c2],   dq.x, s3);
                s0 = fma2(kp[2*c2+1], a.y,  s0);
                s1 = fma2(kp[2*c2+1], bq.y, s1);
                s2 = fma2(kp[2*c2+1], cq.y, s2);
                s3 = fma2(kp[2*c2+1], dq.y, s3);
            }
            float a0, a1, b0, b1, c0, c1, d0, d1;
            unpk(s0, a0, a1); unpk(s1, b0, b1);
            unpk(s2, c0, c1); unpk(s3, d0, d1);
            // ascending candidate order for exact tie-breaking
            tA.insert(fmaxf(a0, 0.f), jt + jj + 0);
            tB.insert(fmaxf(a1, 0.f), jt + jj + 0);
            tA.insert(fmaxf(b0, 0.f), jt + jj + 1);
            tB.insert(fmaxf(b1, 0.f), jt + jj + 1);
            tA.insert(fmaxf(c0, 0.f), jt + jj + 2);
            tB.insert(fmaxf(c1, 0.f), jt + jj + 2);
            tA.insert(fmaxf(d0, 0.f), jt + jj + 3);
            tB.insert(fmaxf(d1, 0.f), jt + jj + 3);
        }
    }

    tA.store(g_idx + ((size_t)b * T + i0) * KNN);
    tB.store(g_idx + ((size_t)b * T + i1) * KNN);
}

// ---------------------------------------------------------------------------
// Kernel 3: gather v + 1x1 conv (576 -> 64) + bias, f32x2 over output pairs.
// v rows fetched warp-cooperatively (coalesced 256B rows) into a padded,
// conflict-free smem tile; weights broadcast from smem as 64-bit pairs.
// ---------------------------------------------------------------------------
__global__ __launch_bounds__(128) void gather_conv_kernel(
    const float* __restrict__ conv_b,
    float* __restrict__ out)
{
    __shared__ float  Ws[C * C];          // 16 KB, [cc][o] for current kk
    __shared__ float4 Vs[4][16][33];      // per warp: [c4][row], pad -> no conflicts

    const int b   = blockIdx.y;
    const int tid = threadIdx.x;
    const int w   = tid >> 5;
    const int l   = tid & 31;
    const int i   = blockIdx.x * 128 + tid;

    u64 accp[32];
    #pragma unroll
    for (int o2 = 0; o2 < 32; o2++) accp[o2] = 0ull;

    const int base = (b * T + i) * KNN;

    for (int kk = 0; kk < KNN; kk++) {
        __syncthreads();   // all reads of Ws/Vs from previous kk complete
        {
            const float4* wsrc = (const float4*)(g_wP + kk * C * C);
            float4* wdst = (float4*)Ws;
            #pragma unroll
            for (int r = 0; r < 8; r++)
                wdst[r * 128 + tid] = wsrc[r * 128 + tid];
        }

        int j = g_idx[base + kk];

        // warp-cooperative staging of this warp's 32 v rows (coalesced)
        #pragma unroll
        for (int rp = 0; rp < 32; rp += 2) {
            int r  = rp + (l >> 4);          // half-warp per row
            int c4 = l & 15;
            int jr = __shfl_sync(0xffffffffu, j, r);
            float4 vv = ((const float4*)(g_vT + ((size_t)b * T + jr) * C))[c4];
            Vs[w][c4][r] = vv;
        }
        __syncthreads();   // Ws ready for all warps; Vs ready for own warp

        #pragma unroll
        for (int c4 = 0; c4 < 16; c4++) {
            float4 xv = Vs[w][c4][l];
            float xs[4] = {xv.x, xv.y, xv.z, xv.w};
            #pragma unroll
            for (int e = 0; e < 4; e++) {
                u64 xd = pk2(xs[e], xs[e]);
                const ulonglong2* wr = (const ulonglong2*)(Ws + (c4 * 4 + e) * C);
                #pragma unroll
                for (int o4 = 0; o4 < 16; o4++) {
                    ulonglong2 wp = wr[o4];
                    accp[2*o4+0] = fma2(xd, wp.x, accp[2*o4+0]);
                    accp[2*o4+1] = fma2(xd, wp.y, accp[2*o4+1]);
                }
            }
        }
    }

    // out[b][o][i] = acc[o] + bias[o]   (coalesced over i)
    #pragma unroll
    for (int o2 = 0; o2 < 32; o2++) {
        float f0, f1;
        unpk(accp[o2], f0, f1);
        out[((size_t)(b * C + 2*o2 + 0)) * T + i] = f0 + __ldg(&conv_b[2*o2 + 0]);
        out[((size_t)(b * C + 2*o2 + 1)) * T + i] = f1 + __ldg(&conv_b[2*o2 + 1]);
    }
}

// ---------------------------------------------------------------------------
extern "C" void kernel_launch(void* const* d_in, const int* in_sizes, int n_in,
                              void* d_out, int out_size)
{
    const float* x      = (const float*)d_in[0];
    const float* Wq     = (const float*)d_in[1];
    const float* Wk     = (const float*)d_in[2];
    const float* Wv     = (const float*)d_in[3];
    const float* conv_w = (const float*)d_in[4];
    const float* conv_b = (const float*)d_in[5];
    float* out          = (float*)d_out;

    permute_w_kernel<<<(KNN * C * C + 255) / 256, 256>>>(conv_w);
    proj_kernel<<<dim3(T / 128, B), 128>>>(x, Wq, Wk, Wv);
    sim_topk_kernel<<<dim3(T / 256, B), 128>>>();
    gather_conv_kernel<<<dim3(T / 128, B), 128>>>(conv_b, out);
}